// round 1
// baseline (speedup 1.0000x reference)
#include <cuda_runtime.h>

// Problem constants
#define NB 32      // batch
#define NT 2048    // tokens
#define ND 1024    // d_token == n_heads*d_head
#define TS 16      // token splits for the reduction
#define TOK (NT/TS)       // 128 tokens per reduce block
#define KSPLIT 4          // K splits per GEMM
#define KSLICE (ND/KSPLIT)    // 256 floats per slice
#define KSLICE4 (KSLICE/4)    // 64 float4 per row slice

// Scratch (allocation-free: __device__ globals)
__device__ float g_partial[TS * NB * ND];      // 8 MB
__device__ float g_xs[NB * ND];                // 128 KB
__device__ float g_xc[KSPLIT][NB * ND];        // GEMM1 partials
__device__ float g_op[KSPLIT][NB * ND];        // GEMM2 partials

// ---------------------------------------------------------------------------
// Stage 1: xs_partial[s][b][:] = sum over tokens [s*TOK, (s+1)*TOK) of x[b,t,:]
// grid (TS, NB), 256 threads; each thread owns one float4 column, 128 tokens.
// ---------------------------------------------------------------------------
__global__ void __launch_bounds__(256) k_reduce(const float* __restrict__ x) {
    const int s = blockIdx.x, b = blockIdx.y, j = threadIdx.x;
    const float4* xp = reinterpret_cast<const float4*>(x)
                     + ((size_t)b * NT + (size_t)s * TOK) * (ND / 4) + j;
    float4 a0 = make_float4(0.f, 0.f, 0.f, 0.f);
    float4 a1 = make_float4(0.f, 0.f, 0.f, 0.f);
    #pragma unroll 4
    for (int t = 0; t < TOK; t += 2) {
        float4 v0 = xp[(size_t)t * (ND / 4)];
        float4 v1 = xp[(size_t)(t + 1) * (ND / 4)];
        a0.x += v0.x; a0.y += v0.y; a0.z += v0.z; a0.w += v0.w;
        a1.x += v1.x; a1.y += v1.y; a1.z += v1.z; a1.w += v1.w;
    }
    float4 r = make_float4(a0.x + a1.x, a0.y + a1.y, a0.z + a1.z, a0.w + a1.w);
    reinterpret_cast<float4*>(g_partial)[(s * NB + b) * (ND / 4) + j] = r;
}

// ---------------------------------------------------------------------------
// Stage 2: xs[b][:] = sum_s partial[s][b][:]
// ---------------------------------------------------------------------------
__global__ void __launch_bounds__(256) k_combine() {
    const int b = blockIdx.x, j = threadIdx.x;
    float4 acc = make_float4(0.f, 0.f, 0.f, 0.f);
    #pragma unroll
    for (int s = 0; s < TS; ++s) {
        float4 v = reinterpret_cast<const float4*>(g_partial)[(s * NB + b) * (ND / 4) + j];
        acc.x += v.x; acc.y += v.y; acc.z += v.z; acc.w += v.w;
    }
    reinterpret_cast<float4*>(g_xs)[b * (ND / 4) + j] = acc;
}

// ---------------------------------------------------------------------------
// Small GEMM: out[b,o] (partial over K slice) = sum_i A[b,i] * W[o,i]
// MODE 0: A = g_xs,               writes g_xc[ks]
// MODE 1: A = sum_p g_xc[p],      writes g_op[ks]
// grid (64, KSPLIT), 256 threads (8 warps). Warp w owns columns o0=bx*16+2w, o0+1.
// Lane j covers float4 K-chunks; acc[b] per lane; butterfly transpose-reduce
// leaves lane l holding the full sum for batch row b=l (static indices only).
// ---------------------------------------------------------------------------
template <int MODE>
__global__ void __launch_bounds__(256) k_gemm(const float* __restrict__ W) {
    __shared__ float4 As[NB * KSLICE4];      // 32 rows x 256-float K slice = 32 KB
    const int tid  = threadIdx.x;
    const int ks   = blockIdx.y;
    const int base4 = ks * KSLICE4;          // float4 offset of this K slice

    // Load A slice into smem (MODE 1 sums the 4 GEMM1 partials on the fly)
    for (int idx = tid; idx < NB * KSLICE4; idx += 256) {
        const int b = idx >> 6, ii = idx & 63;
        float4 v;
        if (MODE == 0) {
            v = reinterpret_cast<const float4*>(g_xs)[b * (ND / 4) + base4 + ii];
        } else {
            v = make_float4(0.f, 0.f, 0.f, 0.f);
            #pragma unroll
            for (int p = 0; p < KSPLIT; ++p) {
                float4 u = reinterpret_cast<const float4*>(g_xc[p])[b * (ND / 4) + base4 + ii];
                v.x += u.x; v.y += u.y; v.z += u.z; v.w += u.w;
            }
        }
        As[idx] = v;
    }
    __syncthreads();

    const int w    = tid >> 5;
    const int lane = tid & 31;
    const int o0   = blockIdx.x * 16 + w * 2;
    const float4* Wr0 = reinterpret_cast<const float4*>(W) + (size_t)o0 * (ND / 4) + base4;
    const float4* Wr1 = Wr0 + (ND / 4);

    float acc0[NB], acc1[NB];
    #pragma unroll
    for (int b = 0; b < NB; ++b) { acc0[b] = 0.f; acc1[b] = 0.f; }

    #pragma unroll
    for (int c = 0; c < KSLICE4 / 32; ++c) {       // 2 iterations
        const float4 w0 = Wr0[c * 32 + lane];
        const float4 w1 = Wr1[c * 32 + lane];
        #pragma unroll
        for (int b = 0; b < NB; ++b) {
            const float4 a = As[b * KSLICE4 + c * 32 + lane];
            acc0[b] += w0.x * a.x; acc0[b] += w0.y * a.y;
            acc0[b] += w0.z * a.z; acc0[b] += w0.w * a.w;
            acc1[b] += w1.x * a.x; acc1[b] += w1.y * a.y;
            acc1[b] += w1.z * a.z; acc1[b] += w1.w * a.w;
        }
    }

    // Butterfly transpose-reduce: after all stages lane l holds acc*[0] = row b=l.
#define RSTAGE(OFF)                                                            \
    {                                                                          \
        const bool up = (lane & (OFF)) != 0;                                   \
        _Pragma("unroll")                                                      \
        for (int b = 0; b < (OFF); ++b) {                                      \
            float k0 = up ? acc0[b + (OFF)] : acc0[b];                         \
            float s0 = up ? acc0[b] : acc0[b + (OFF)];                         \
            acc0[b] = k0 + __shfl_xor_sync(0xffffffffu, s0, (OFF));            \
            float k1 = up ? acc1[b + (OFF)] : acc1[b];                         \
            float s1 = up ? acc1[b] : acc1[b + (OFF)];                         \
            acc1[b] = k1 + __shfl_xor_sync(0xffffffffu, s1, (OFF));            \
        }                                                                      \
    }
    RSTAGE(16) RSTAGE(8) RSTAGE(4) RSTAGE(2) RSTAGE(1)
#undef RSTAGE

    float* outp = (MODE == 0) ? g_xc[ks] : g_op[ks];
    outp[lane * ND + o0]     = acc0[0];
    outp[lane * ND + o0 + 1] = acc1[0];
}

// ---------------------------------------------------------------------------
// Epilogue: out[b,c] = sum_p g_op[p][b,c] + bias[c]
// ---------------------------------------------------------------------------
__global__ void __launch_bounds__(256) k_epi(const float* __restrict__ bias,
                                             float* __restrict__ out) {
    const int b = blockIdx.x, j = threadIdx.x;
    float4 acc = reinterpret_cast<const float4*>(bias)[j];
    #pragma unroll
    for (int p = 0; p < KSPLIT; ++p) {
        float4 v = reinterpret_cast<const float4*>(g_op[p])[b * (ND / 4) + j];
        acc.x += v.x; acc.y += v.y; acc.z += v.z; acc.w += v.w;
    }
    reinterpret_cast<float4*>(out)[b * (ND / 4) + j] = acc;
}

// ---------------------------------------------------------------------------
extern "C" void kernel_launch(void* const* d_in, const int* in_sizes, int n_in,
                              void* d_out, int out_size) {
    const float* x  = (const float*)d_in[0];   // [32, 2048, 1024]
    const float* Wh = (const float*)d_in[1];   // [16, 64, 1024] -> flat [1024,1024]
    const float* Wp = (const float*)d_in[2];   // [1024, 1024]
    const float* bp = (const float*)d_in[3];   // [1024]
    float* out = (float*)d_out;                // [32, 1024]

    k_reduce<<<dim3(TS, NB), 256>>>(x);
    k_combine<<<NB, 256>>>();
    k_gemm<0><<<dim3(ND / 16, KSPLIT), 256>>>(Wh);
    k_gemm<1><<<dim3(ND / 16, KSPLIT), 256>>>(Wp);
    k_epi<<<NB, 256>>>(bp, out);
}

// round 2
// speedup vs baseline: 1.0398x; 1.0398x over previous
#include <cuda_runtime.h>

#define NB 32      // batch
#define NT 2048    // tokens
#define ND 1024    // d_token == n_heads*d_head
#define TS 16      // token splits for the reduction
#define TOK (NT/TS)
#define KS2 8      // GEMM K-splits (K-slice = 128 floats = 32 float4)
#define OT 64      // o-columns per GEMM block tile

// Scratch (allocation-free: __device__ globals)
__device__ float g_partial[TS * NB * ND];   // 8 MB reduce partials
__device__ float g_xs[NB * ND];             // token-summed x
__device__ float g_xc[KS2][NB * ND];        // GEMM1 K-split partials
__device__ float g_xh[NB * ND];             // combined head activations
__device__ float g_op[KS2][NB * ND];        // GEMM2 K-split partials

// ---------------------------------------------------------------------------
// Stage 1: partial[s][b][:] = sum over tokens [s*TOK,(s+1)*TOK) of x[b,t,:]
// HBM-bound: 256 MB read. grid (TS, NB) = 512 blocks, 256 thr.
// ---------------------------------------------------------------------------
__global__ void __launch_bounds__(256) k_reduce(const float* __restrict__ x) {
    const int s = blockIdx.x, b = blockIdx.y, j = threadIdx.x;
    const float4* xp = reinterpret_cast<const float4*>(x)
                     + ((size_t)b * NT + (size_t)s * TOK) * (ND / 4) + j;
    float4 a0 = make_float4(0.f, 0.f, 0.f, 0.f);
    float4 a1 = make_float4(0.f, 0.f, 0.f, 0.f);
    #pragma unroll 4
    for (int t = 0; t < TOK; t += 2) {
        float4 v0 = xp[(size_t)t * (ND / 4)];
        float4 v1 = xp[(size_t)(t + 1) * (ND / 4)];
        a0.x += v0.x; a0.y += v0.y; a0.z += v0.z; a0.w += v0.w;
        a1.x += v1.x; a1.y += v1.y; a1.z += v1.z; a1.w += v1.w;
    }
    float4 r = make_float4(a0.x + a1.x, a0.y + a1.y, a0.z + a1.z, a0.w + a1.w);
    reinterpret_cast<float4*>(g_partial)[(s * NB + b) * (ND / 4) + j] = r;
}

// ---------------------------------------------------------------------------
// Generic partial fold. MODE 0: g_partial(16) -> g_xs. MODE 1: g_xc(8) -> g_xh.
// grid 32 x 256 thr, one float4 per thread.
// ---------------------------------------------------------------------------
template <int MODE>
__global__ void __launch_bounds__(256) k_combine() {
    const int NS = (MODE == 0) ? TS : KS2;
    const float* src = (MODE == 0) ? g_partial : &g_xc[0][0];
    float* dst = (MODE == 0) ? g_xs : g_xh;
    const int i = blockIdx.x * 256 + threadIdx.x;
    float4 acc = make_float4(0.f, 0.f, 0.f, 0.f);
    #pragma unroll
    for (int s = 0; s < NS; ++s) {
        float4 v = reinterpret_cast<const float4*>(src)[s * (NB * ND / 4) + i];
        acc.x += v.x; acc.y += v.y; acc.z += v.z; acc.w += v.w;
    }
    reinterpret_cast<float4*>(dst)[i] = acc;
}

// ---------------------------------------------------------------------------
// GEMM: dst[b,o] (partial over K-slice) = sum_d A[b,d] * W[o,d]
// Block tile: 64 o x 32 b x 128 K. grid (ND/OT=16, KS2=8) = 128 blocks, 256 thr.
// Thread (ox=tid&31, by=tid>>5) owns o in {otile+ox, otile+32+ox},
// b in {by, by+8, by+16, by+24}: 8 accumulators, NO cross-lane reduction.
// A smem [b][d4]: warp-uniform reads (broadcast). W smem [d4][o] with
// add-rotate swizzle (o+d4)&63: conflict-free stores AND loads. 48 KB total.
// ---------------------------------------------------------------------------
template <int MODE>
__global__ void __launch_bounds__(256) k_gemm(const float* __restrict__ W) {
    __shared__ float4 As[NB * 32];    // 16 KB
    __shared__ float4 Ws[32 * OT];    // 32 KB
    const float* A = (MODE == 0) ? g_xs : g_xh;
    const int tid    = threadIdx.x;
    const int otile  = blockIdx.x * OT;
    const int kbase4 = blockIdx.y * 32;   // float4 offset of K-slice

    // Load A slice [32 b][32 d4] — coalesced, conflict-free
    {
        const int b = tid >> 5, d4 = tid & 31;
        #pragma unroll
        for (int r = 0; r < 4; ++r)
            As[(b + r * 8) * 32 + d4] =
                reinterpret_cast<const float4*>(A)[(b + r * 8) * (ND / 4) + kbase4 + d4];
    }
    // Load W slice [64 o][32 d4] -> swizzled [d4][(o+d4)&63]
    {
        const int o = tid >> 5, d4 = tid & 31;
        #pragma unroll
        for (int r = 0; r < 8; ++r) {
            const int oo = o + r * 8;
            Ws[d4 * OT + ((oo + d4) & 63)] =
                reinterpret_cast<const float4*>(W)[(size_t)(otile + oo) * (ND / 4) + kbase4 + d4];
        }
    }
    __syncthreads();

    const int ox = tid & 31;
    const int by = tid >> 5;

    float acc[4][2];
    #pragma unroll
    for (int bi = 0; bi < 4; ++bi) { acc[bi][0] = 0.f; acc[bi][1] = 0.f; }

    #pragma unroll 8
    for (int d4 = 0; d4 < 32; ++d4) {
        const float4 w0 = Ws[d4 * OT + ((ox + d4) & 63)];
        const float4 w1 = Ws[d4 * OT + ((ox + 32 + d4) & 63)];
        #pragma unroll
        for (int bi = 0; bi < 4; ++bi) {
            const float4 a = As[(by + bi * 8) * 32 + d4];
            acc[bi][0] += a.x * w0.x; acc[bi][0] += a.y * w0.y;
            acc[bi][0] += a.z * w0.z; acc[bi][0] += a.w * w0.w;
            acc[bi][1] += a.x * w1.x; acc[bi][1] += a.y * w1.y;
            acc[bi][1] += a.z * w1.z; acc[bi][1] += a.w * w1.w;
        }
    }

    float* dst = (MODE == 0) ? g_xc[blockIdx.y] : g_op[blockIdx.y];
    #pragma unroll
    for (int bi = 0; bi < 4; ++bi) {
        const int b = by + bi * 8;
        dst[b * ND + otile + ox]      = acc[bi][0];
        dst[b * ND + otile + 32 + ox] = acc[bi][1];
    }
}

// ---------------------------------------------------------------------------
// Epilogue: out[b,c] = sum_p g_op[p][b,c] + bias[c]
// ---------------------------------------------------------------------------
__global__ void __launch_bounds__(256) k_epi(const float* __restrict__ bias,
                                             float* __restrict__ out) {
    const int b = blockIdx.x, j = threadIdx.x;
    float4 acc = reinterpret_cast<const float4*>(bias)[j];
    #pragma unroll
    for (int p = 0; p < KS2; ++p) {
        float4 v = reinterpret_cast<const float4*>(g_op[p])[b * (ND / 4) + j];
        acc.x += v.x; acc.y += v.y; acc.z += v.z; acc.w += v.w;
    }
    reinterpret_cast<float4*>(out)[b * (ND / 4) + j] = acc;
}

// ---------------------------------------------------------------------------
extern "C" void kernel_launch(void* const* d_in, const int* in_sizes, int n_in,
                              void* d_out, int out_size) {
    const float* x  = (const float*)d_in[0];   // [32, 2048, 1024]
    const float* Wh = (const float*)d_in[1];   // [16, 64, 1024] -> flat [1024,1024]
    const float* Wp = (const float*)d_in[2];   // [1024, 1024]
    const float* bp = (const float*)d_in[3];   // [1024]
    float* out = (float*)d_out;                // [32, 1024]

    k_reduce<<<dim3(TS, NB), 256>>>(x);
    k_combine<0><<<NB * ND / 4 / 256, 256>>>();
    k_gemm<0><<<dim3(ND / OT, KS2), 256>>>(Wh);
    k_combine<1><<<NB * ND / 4 / 256, 256>>>();
    k_gemm<1><<<dim3(ND / OT, KS2), 256>>>(Wp);
    k_epi<<<NB, 256>>>(bp, out);
}